// round 4
// baseline (speedup 1.0000x reference)
#include <cuda_runtime.h>

#define Bn 32
#define Tn 128
#define In 256
#define Hn 256
#define IH 512
#define On 128
#define NBLK 128      // persistent blocks; 128 KB smem => 1 block/SM
#define NTHR 512      // 16 warps
#define NW   16

__device__ float g_h[2][Bn * Hn];                 // ping-pong hidden state
__device__ __align__(16) unsigned g_arr[NBLK];    // per-block arrival counters

// ---------------------------------------------------------------------------
__global__ void init_kernel()
{
    int i = blockIdx.x * blockDim.x + threadIdx.x;
    if (i < NBLK) g_arr[i] = 0u;
    for (int k = i; k < Bn * Hn; k += gridDim.x * blockDim.x) g_h[0][k] = 0.f;
}

// ---------------------------------------------------------------------------
__device__ __forceinline__ float warp_sum(float v)
{
#pragma unroll
    for (int o = 16; o > 0; o >>= 1) v += __shfl_xor_sync(0xffffffffu, v, o);
    return v;
}
__device__ __forceinline__ float tanh_fast(float v)
{
    float r; asm("tanh.approx.f32 %0, %1;" : "=f"(r) : "f"(v)); return r;
}
__device__ __forceinline__ void red_release(unsigned* p)
{
    asm volatile("red.release.gpu.global.add.u32 [%0], 1;" :: "l"(p) : "memory");
}
__device__ __forceinline__ uint4 ld_acq_v4(const unsigned* p)
{
    uint4 v;
    asm volatile("ld.acquire.gpu.global.v4.u32 {%0,%1,%2,%3}, [%4];"
                 : "=r"(v.x), "=r"(v.y), "=r"(v.z), "=r"(v.w) : "l"(p) : "memory");
    return v;
}
__device__ __forceinline__ float d4(float4 a, float4 b)
{
    return a.x * b.x + a.y * b.y + a.z * b.z + a.w * b.w;
}
// Warp-autonomous wait: all 128 per-block counters >= target.
__device__ __forceinline__ void wait_all(int lane, unsigned target)
{
    const unsigned* p = g_arr + lane * 4;
    for (;;) {
        uint4 c = ld_acq_v4(p);
        bool ok = (c.x >= target) & (c.y >= target) & (c.z >= target) & (c.w >= target);
        if (__all_sync(0xffffffffu, ok)) break;
        __nanosleep(40);
    }
}

// ---------------------------------------------------------------------------
// Persistent kernel. Block owns h-rows {2*bid, 2*bid+1} x 32 batches; F slice
// (64 rows x 512) lives in smem for all steps. Warp w: r=w>>3, bi0=w&7 ->
// rows warp-PRIVATE => no bar.sync / membar in the main loop. Sync is purely
// per-warp: red.release arrive on g_arr[bid], acquire-poll of all counters.
// ---------------------------------------------------------------------------
__global__ __launch_bounds__(NTHR, 1) void persist_kernel(
    const float* __restrict__ x,
    const float* __restrict__ Wl,
    const float* __restrict__ Wg,
    const float* __restrict__ W,
    const float* __restrict__ bias,
    const float* __restrict__ Wout,
    const float* __restrict__ bout,
    float* __restrict__ out)
{
    extern __shared__ float F_sm[];            // 64 * 512 floats = 128 KB
    float4* __restrict__ F4 = (float4*)F_sm;   // [64][128]

    const int tid  = threadIdx.x;
    const int wid  = tid >> 5, lane = tid & 31;
    const int r    = wid >> 3;
    const int bi0  = wid & 7;
    const int h    = blockIdx.x * 2 + r;

    // Pin this warp's weight-row slices in registers for the whole kernel.
    float4 w4[4], l4[4], g4[4];
    {
        const float4* Wp = (const float4*)(W  + (size_t)h * IH);
        const float4* Lp = (const float4*)(Wl + (size_t)h * IH);
        const float4* Gp = (const float4*)(Wg + (size_t)h * IH);
#pragma unroll
        for (int k = 0; k < 4; k++) {
            int f4 = k * 32 + lane;
            w4[k] = __ldg(Wp + f4);
            l4[k] = __ldg(Lp + f4);
            g4[k] = __ldg(Gp + f4);
        }
    }
    const float bia = __ldg(bias + h);

    // Zero this warp's own F rows (warp-private => no sync needed).
    {
        float4 z = make_float4(0.f, 0.f, 0.f, 0.f);
#pragma unroll
        for (int u = 0; u < 4; u++) {
            float4* Fr = F4 + (r * 32 + bi0 + u * 8) * (IH / 4);
#pragma unroll
            for (int k = 0; k < 4; k++) Fr[k * 32 + lane] = z;
        }
    }

    for (int t = 0; t < Tn; t++) {
        const float4* __restrict__ hin = (const float4*)g_h[t & 1];
        float* __restrict__ hout = g_h[(t & 1) ^ 1];

        float ssp[4], dxp[4], rn[4];

        // ---------- phase A: barrier-independent (own F rows + x) ----------
#pragma unroll
        for (int u = 0; u < 4; u++) {
            const int bi = bi0 + u * 8;
            const float4* __restrict__ xr = (const float4*)(x + ((size_t)bi * Tn + t) * In);
            const float4* __restrict__ Fr = F4 + (r * 32 + bi) * (IH / 4);

            float4 Fv0 = Fr[lane],      Fv1 = Fr[32 + lane];
            float4 Fv2 = Fr[64 + lane], Fv3 = Fr[96 + lane];
            float4 tw0, tw1, tw2, tw3;
            tw0.x = w4[0].x + Fv0.x; tw0.y = w4[0].y + Fv0.y; tw0.z = w4[0].z + Fv0.z; tw0.w = w4[0].w + Fv0.w;
            tw1.x = w4[1].x + Fv1.x; tw1.y = w4[1].y + Fv1.y; tw1.z = w4[1].z + Fv1.z; tw1.w = w4[1].w + Fv1.w;
            tw2.x = w4[2].x + Fv2.x; tw2.y = w4[2].y + Fv2.y; tw2.z = w4[2].z + Fv2.z; tw2.w = w4[2].w + Fv2.w;
            tw3.x = w4[3].x + Fv3.x; tw3.y = w4[3].y + Fv3.y; tw3.z = w4[3].z + Fv3.z; tw3.w = w4[3].w + Fv3.w;

            float4 xv0 = __ldg(xr + lane);
            float4 xv1 = __ldg(xr + 32 + lane);
            float ssa = d4(tw0, tw0) + d4(tw2, tw2);
            float ssb = d4(tw1, tw1) + d4(tw3, tw3);
            ssp[u] = ssa + ssb;
            dxp[u] = d4(xv0, tw0) + d4(xv1, tw1);
        }
        // 4 interleaved butterfly chains (independent -> latency-hidden).
#pragma unroll
        for (int o = 16; o > 0; o >>= 1) {
            ssp[0] += __shfl_xor_sync(0xffffffffu, ssp[0], o);
            ssp[1] += __shfl_xor_sync(0xffffffffu, ssp[1], o);
            ssp[2] += __shfl_xor_sync(0xffffffffu, ssp[2], o);
            ssp[3] += __shfl_xor_sync(0xffffffffu, ssp[3], o);
        }
#pragma unroll
        for (int u = 0; u < 4; u++) rn[u] = rsqrtf(ssp[u]);

        // ---------- wait: h(t-1) published by all blocks ----------
        wait_all(lane, (unsigned)(NW * t));

        // ---------- phase B: critical path, h-prefetch 1 batch ahead ----------
        float4 ha = __ldcg(hin + bi0 * (Hn / 4) + lane);
        float4 hb = __ldcg(hin + bi0 * (Hn / 4) + 32 + lane);
#pragma unroll
        for (int u = 0; u < 4; u++) {
            const int bi = bi0 + u * 8;
            float4 han, hbn;
            if (u < 3) {
                han = __ldcg(hin + (bi + 8) * (Hn / 4) + lane);
                hbn = __ldcg(hin + (bi + 8) * (Hn / 4) + 32 + lane);
            }
            const float4* __restrict__ xr = (const float4*)(x + ((size_t)bi * Tn + t) * In);
            float4* __restrict__ Fr = F4 + (r * 32 + bi) * (IH / 4);

            float4 Fv2 = Fr[64 + lane], Fv3 = Fr[96 + lane];
            float4 tw2, tw3;
            tw2.x = w4[2].x + Fv2.x; tw2.y = w4[2].y + Fv2.y; tw2.z = w4[2].z + Fv2.z; tw2.w = w4[2].w + Fv2.w;
            tw3.x = w4[3].x + Fv3.x; tw3.y = w4[3].y + Fv3.y; tw3.z = w4[3].z + Fv3.z; tw3.w = w4[3].w + Fv3.w;

            float tot = warp_sum(dxp[u] + d4(ha, tw2) + d4(hb, tw3));
            const float rr = rn[u];
            const float hn = tanh_fast(tot + bia) * rr;

            float4 xv0 = __ldg(xr + lane);        // L1 hit (loaded in phase A)
            float4 xv1 = __ldg(xr + 32 + lane);
            float4 Fv0 = Fr[lane], Fv1 = Fr[32 + lane];
            float4 o;
            o.x = l4[0].x * (Fv0.x * rr) + g4[0].x * (xv0.x * hn);
            o.y = l4[0].y * (Fv0.y * rr) + g4[0].y * (xv0.y * hn);
            o.z = l4[0].z * (Fv0.z * rr) + g4[0].z * (xv0.z * hn);
            o.w = l4[0].w * (Fv0.w * rr) + g4[0].w * (xv0.w * hn);
            Fr[lane] = o;
            o.x = l4[1].x * (Fv1.x * rr) + g4[1].x * (xv1.x * hn);
            o.y = l4[1].y * (Fv1.y * rr) + g4[1].y * (xv1.y * hn);
            o.z = l4[1].z * (Fv1.z * rr) + g4[1].z * (xv1.z * hn);
            o.w = l4[1].w * (Fv1.w * rr) + g4[1].w * (xv1.w * hn);
            Fr[32 + lane] = o;
            o.x = l4[2].x * (Fv2.x * rr) + g4[2].x * (ha.x * hn);
            o.y = l4[2].y * (Fv2.y * rr) + g4[2].y * (ha.y * hn);
            o.z = l4[2].z * (Fv2.z * rr) + g4[2].z * (ha.z * hn);
            o.w = l4[2].w * (Fv2.w * rr) + g4[2].w * (ha.w * hn);
            Fr[64 + lane] = o;
            o.x = l4[3].x * (Fv3.x * rr) + g4[3].x * (hb.x * hn);
            o.y = l4[3].y * (Fv3.y * rr) + g4[3].y * (hb.y * hn);
            o.z = l4[3].z * (Fv3.z * rr) + g4[3].z * (hb.z * hn);
            o.w = l4[3].w * (Fv3.w * rr) + g4[3].w * (hb.w * hn);
            Fr[96 + lane] = o;

            if (lane == 0) hout[bi * Hn + h] = hn;
            ha = han; hb = hbn;
        }
        // ---------- arrive (per-warp; release orders lane-0's h STGs) ----------
        if (lane == 0) red_release(&g_arr[blockIdx.x]);
    }

    // ---- F writeout: cross-warp smem reads -> one bar.sync first ----
    __syncthreads();
    float* __restrict__ Fout = out + Bn * On + Bn * Hn;
    float4* __restrict__ Fo4 = (float4*)Fout;
    for (int j = wid; j < 64; j += NW) {
        int rr = j >> 5, bb = j & 31;
        int grow = bb * Hn + blockIdx.x * 2 + rr;
#pragma unroll
        for (int k = 0; k < 4; k++) {
            int f4 = k * 32 + lane;
            Fo4[(size_t)grow * (IH / 4) + f4] = F4[j * (IH / 4) + f4];
        }
    }

    // ---- epilogue: needs all blocks' final h ----
    if (blockIdx.x < 64) {
        wait_all(lane, (unsigned)(NW * Tn));
    }
    if (blockIdx.x < 32) {
        const int b = blockIdx.x;
        __syncthreads();                 // Fout reads of F_sm done; reuse as h cache
        for (int i = tid; i < Hn; i += NTHR)
            F_sm[i] = __ldcg(&g_h[0][b * Hn + i]);   // T even -> final h in buf 0
        __syncthreads();
        const float4* hv4 = (const float4*)F_sm;
        for (int o = wid; o < On; o += NW) {
            const float4* wr = (const float4*)(Wout + (size_t)o * Hn);
            float acc = 0.f;
#pragma unroll
            for (int k = 0; k < 2; k++) {
                int j4 = k * 32 + lane;
                acc += d4(__ldg(wr + j4), hv4[j4]);
            }
            acc = warp_sum(acc);
            if (lane == 0) out[b * On + o] = acc + __ldg(bout + o);
        }
    } else if (blockIdx.x < 64) {
        const int b = blockIdx.x - 32;
        for (int i = tid; i < Hn; i += NTHR)
            out[Bn * On + b * Hn + i] = __ldcg(&g_h[0][b * Hn + i]);
    }
}

// ---------------------------------------------------------------------------
extern "C" void kernel_launch(void* const* d_in, const int* in_sizes, int n_in,
                              void* d_out, int out_size)
{
    const float* sentence = (const float*)d_in[0];
    const float* Wl   = (const float*)d_in[1];
    const float* Wg   = (const float*)d_in[2];
    const float* W    = (const float*)d_in[3];
    const float* bias = (const float*)d_in[4];
    const float* Wout = (const float*)d_in[5];
    const float* bout = (const float*)d_in[6];
    float* out = (float*)d_out;

    const int smem = 64 * IH * sizeof(float);  // 131072
    cudaFuncSetAttribute(persist_kernel, cudaFuncAttributeMaxDynamicSharedMemorySize, smem);

    init_kernel<<<32, 256>>>();
    persist_kernel<<<NBLK, NTHR, smem>>>(sentence, Wl, Wg, W, bias, Wout, bout, out);
}

// round 5
// speedup vs baseline: 3.5426x; 3.5426x over previous
#include <cuda_runtime.h>

#define Bn 32
#define Tn 128
#define In 256
#define Hn 256
#define IH 512
#define On 128
#define NBLK 256      // persistent blocks; 64 KB smem, <=128 regs => 2 blocks/SM
#define NTHR 256      // 8 warps

__device__ float g_h[2][Bn * Hn];   // ping-pong hidden state
__device__ unsigned g_bar;          // monotonic grid-barrier counter

// ---------------------------------------------------------------------------
__global__ void init_kernel()
{
    int i = blockIdx.x * blockDim.x + threadIdx.x;
    if (i == 0) g_bar = 0u;
    for (int k = i; k < Bn * Hn; k += gridDim.x * blockDim.x) g_h[0][k] = 0.f;
}

// ---------------------------------------------------------------------------
__device__ __forceinline__ float warp_sum(float v)
{
#pragma unroll
    for (int o = 16; o > 0; o >>= 1) v += __shfl_xor_sync(0xffffffffu, v, o);
    return v;
}
__device__ __forceinline__ float tanh_fast(float v)
{
    float r; asm("tanh.approx.f32 %0, %1;" : "=f"(r) : "f"(v)); return r;
}
__device__ __forceinline__ unsigned ld_acquire(const unsigned* p)
{
    unsigned v;
    asm volatile("ld.acquire.gpu.global.u32 %0, [%1];" : "=r"(v) : "l"(p) : "memory");
    return v;
}
__device__ __forceinline__ void red_release(unsigned* p)
{
    asm volatile("red.release.gpu.global.add.u32 [%0], 1;" :: "l"(p) : "memory");
}
__device__ __forceinline__ float d4(float4 a, float4 b)
{
    return a.x * b.x + a.y * b.y + a.z * b.z + a.w * b.w;
}

// ---------------------------------------------------------------------------
// Persistent kernel, 2 blocks/SM. Block owns h-row bid x 32 batches; F slice
// (32 rows x 512 f = 64 KB) in smem for all 128 steps. Warp w (of 8) handles
// batches w + {0,8,16,24}. Lane f-slice: float4 idx f4 = k*32+lane, k=0..3.
//
// Sync per step (CG-style, no threadfence):
//   A (local) -> leader acquire-poll -> bar.sync -> B (critical) -> bar.sync
//   -> leader red.release
// ---------------------------------------------------------------------------
__global__ __launch_bounds__(NTHR, 2) void persist_kernel(
    const float* __restrict__ x,
    const float* __restrict__ Wl,
    const float* __restrict__ Wg,
    const float* __restrict__ W,
    const float* __restrict__ bias,
    const float* __restrict__ Wout,
    const float* __restrict__ bout,
    float* __restrict__ out)
{
    extern __shared__ float F_sm[];            // 32 * 512 floats = 64 KB
    float4* __restrict__ F4 = (float4*)F_sm;   // [32][128]

    const int tid  = threadIdx.x;
    const int wid  = tid >> 5, lane = tid & 31;
    const int bi0  = wid;                      // 0..7
    const int h    = blockIdx.x;

    // Pin this block's weight-row slices in registers (one row per block).
    float4 w4[4], l4[4], g4[4];
    {
        const float4* Wp = (const float4*)(W  + (size_t)h * IH);
        const float4* Lp = (const float4*)(Wl + (size_t)h * IH);
        const float4* Gp = (const float4*)(Wg + (size_t)h * IH);
#pragma unroll
        for (int k = 0; k < 4; k++) {
            int f4 = k * 32 + lane;
            w4[k] = __ldg(Wp + f4);
            l4[k] = __ldg(Lp + f4);
            g4[k] = __ldg(Gp + f4);
        }
    }
    const float bia = __ldg(bias + h);

    // Zero this warp's F rows (warp-private).
    {
        float4 z = make_float4(0.f, 0.f, 0.f, 0.f);
#pragma unroll
        for (int u = 0; u < 4; u++) {
            float4* Fr = F4 + (bi0 + u * 8) * (IH / 4);
#pragma unroll
            for (int k = 0; k < 4; k++) Fr[k * 32 + lane] = z;
        }
    }

    for (int t = 0; t < Tn; t++) {
        const float4* __restrict__ hin = (const float4*)g_h[t & 1];
        float* __restrict__ hout = g_h[(t & 1) ^ 1];

        float ssp[4], dxp[4], rn[4];

        // ---------- phase A: barrier-independent (own F rows + x) ----------
#pragma unroll
        for (int u = 0; u < 4; u++) {
            const int bi = bi0 + u * 8;
            const float4* __restrict__ xr = (const float4*)(x + ((size_t)bi * Tn + t) * In);
            const float4* __restrict__ Fr = F4 + bi * (IH / 4);

            float4 Fv0 = Fr[lane],      Fv1 = Fr[32 + lane];
            float4 Fv2 = Fr[64 + lane], Fv3 = Fr[96 + lane];
            float4 tw0, tw1, tw2, tw3;
            tw0.x = w4[0].x + Fv0.x; tw0.y = w4[0].y + Fv0.y; tw0.z = w4[0].z + Fv0.z; tw0.w = w4[0].w + Fv0.w;
            tw1.x = w4[1].x + Fv1.x; tw1.y = w4[1].y + Fv1.y; tw1.z = w4[1].z + Fv1.z; tw1.w = w4[1].w + Fv1.w;
            tw2.x = w4[2].x + Fv2.x; tw2.y = w4[2].y + Fv2.y; tw2.z = w4[2].z + Fv2.z; tw2.w = w4[2].w + Fv2.w;
            tw3.x = w4[3].x + Fv3.x; tw3.y = w4[3].y + Fv3.y; tw3.z = w4[3].z + Fv3.z; tw3.w = w4[3].w + Fv3.w;

            float4 xv0 = __ldg(xr + lane);
            float4 xv1 = __ldg(xr + 32 + lane);
            float ssa = d4(tw0, tw0) + d4(tw2, tw2);
            float ssb = d4(tw1, tw1) + d4(tw3, tw3);
            ssp[u] = ssa + ssb;
            dxp[u] = d4(xv0, tw0) + d4(xv1, tw1);
        }
        // 4 interleaved butterfly chains.
#pragma unroll
        for (int o = 16; o > 0; o >>= 1) {
            ssp[0] += __shfl_xor_sync(0xffffffffu, ssp[0], o);
            ssp[1] += __shfl_xor_sync(0xffffffffu, ssp[1], o);
            ssp[2] += __shfl_xor_sync(0xffffffffu, ssp[2], o);
            ssp[3] += __shfl_xor_sync(0xffffffffu, ssp[3], o);
        }
#pragma unroll
        for (int u = 0; u < 4; u++) rn[u] = rsqrtf(ssp[u]);

        // ---------- wait: h(t-1) published by all blocks ----------
        if (tid == 0) {
            const unsigned target = (unsigned)NBLK * (unsigned)t;
            while (ld_acquire(&g_bar) < target) __nanosleep(32);
        }
        __syncthreads();

        // ---------- phase B: critical path, h prefetched 1 batch ahead ----------
        float4 ha = __ldcg(hin + bi0 * (Hn / 4) + lane);
        float4 hb = __ldcg(hin + bi0 * (Hn / 4) + 32 + lane);
#pragma unroll
        for (int u = 0; u < 4; u++) {
            const int bi = bi0 + u * 8;
            float4 han, hbn;
            if (u < 3) {
                han = __ldcg(hin + (bi + 8) * (Hn / 4) + lane);
                hbn = __ldcg(hin + (bi + 8) * (Hn / 4) + 32 + lane);
            }
            const float4* __restrict__ xr = (const float4*)(x + ((size_t)bi * Tn + t) * In);
            float4* __restrict__ Fr = F4 + bi * (IH / 4);

            float4 Fv2 = Fr[64 + lane], Fv3 = Fr[96 + lane];
            float4 tw2, tw3;
            tw2.x = w4[2].x + Fv2.x; tw2.y = w4[2].y + Fv2.y; tw2.z = w4[2].z + Fv2.z; tw2.w = w4[2].w + Fv2.w;
            tw3.x = w4[3].x + Fv3.x; tw3.y = w4[3].y + Fv3.y; tw3.z = w4[3].z + Fv3.z; tw3.w = w4[3].w + Fv3.w;

            float tot = warp_sum(dxp[u] + d4(ha, tw2) + d4(hb, tw3));
            const float rr = rn[u];
            const float hn = tanh_fast(tot + bia) * rr;

            float4 xv0 = __ldg(xr + lane);        // L1 hits (phase A)
            float4 xv1 = __ldg(xr + 32 + lane);
            float4 Fv0 = Fr[lane], Fv1 = Fr[32 + lane];
            float4 o;
            o.x = l4[0].x * (Fv0.x * rr) + g4[0].x * (xv0.x * hn);
            o.y = l4[0].y * (Fv0.y * rr) + g4[0].y * (xv0.y * hn);
            o.z = l4[0].z * (Fv0.z * rr) + g4[0].z * (xv0.z * hn);
            o.w = l4[0].w * (Fv0.w * rr) + g4[0].w * (xv0.w * hn);
            Fr[lane] = o;
            o.x = l4[1].x * (Fv1.x * rr) + g4[1].x * (xv1.x * hn);
            o.y = l4[1].y * (Fv1.y * rr) + g4[1].y * (xv1.y * hn);
            o.z = l4[1].z * (Fv1.z * rr) + g4[1].z * (xv1.z * hn);
            o.w = l4[1].w * (Fv1.w * rr) + g4[1].w * (xv1.w * hn);
            Fr[32 + lane] = o;
            o.x = l4[2].x * (Fv2.x * rr) + g4[2].x * (ha.x * hn);
            o.y = l4[2].y * (Fv2.y * rr) + g4[2].y * (ha.y * hn);
            o.z = l4[2].z * (Fv2.z * rr) + g4[2].z * (ha.z * hn);
            o.w = l4[2].w * (Fv2.w * rr) + g4[2].w * (ha.w * hn);
            Fr[64 + lane] = o;
            o.x = l4[3].x * (Fv3.x * rr) + g4[3].x * (hb.x * hn);
            o.y = l4[3].y * (Fv3.y * rr) + g4[3].y * (hb.y * hn);
            o.z = l4[3].z * (Fv3.z * rr) + g4[3].z * (hb.z * hn);
            o.w = l4[3].w * (Fv3.w * rr) + g4[3].w * (hb.w * hn);
            Fr[96 + lane] = o;

            if (lane == 0) hout[bi * Hn + h] = hn;
            ha = han; hb = hbn;
        }

        // ---------- arrive (CG-style: bar.sync then leader release) ----------
        __syncthreads();
        if (tid == 0) red_release(&g_bar);
    }

    // ---- F writeout (warp-private rows; no extra sync needed) ----
    float* __restrict__ Fout = out + Bn * On + Bn * Hn;
    float4* __restrict__ Fo4 = (float4*)Fout;
#pragma unroll
    for (int u = 0; u < 4; u++) {
        const int bb = bi0 + u * 8;
        const int grow = bb * Hn + h;
        const float4* Fr = F4 + bb * (IH / 4);
#pragma unroll
        for (int k = 0; k < 4; k++) {
            int f4 = k * 32 + lane;
            Fo4[(size_t)grow * (IH / 4) + f4] = Fr[f4];
        }
    }

    // ---- epilogue: needs all blocks' final h ----
    if (blockIdx.x < 64) {
        if (tid == 0) {
            const unsigned target = (unsigned)NBLK * (unsigned)Tn;
            while (ld_acquire(&g_bar) < target) __nanosleep(32);
        }
        __syncthreads();
    }

    if (blockIdx.x < 32) {
        const int b = blockIdx.x;
        for (int i = tid; i < Hn; i += NTHR)
            F_sm[i] = __ldcg(&g_h[0][b * Hn + i]);   // T even -> final h in buf 0
        __syncthreads();
        const float4* hv4 = (const float4*)F_sm;
        for (int o = wid; o < On; o += 8) {
            const float4* wr = (const float4*)(Wout + (size_t)o * Hn);
            float acc = 0.f;
#pragma unroll
            for (int k = 0; k < 2; k++) {
                int j4 = k * 32 + lane;
                acc += d4(__ldg(wr + j4), hv4[j4]);
            }
            acc = warp_sum(acc);
            if (lane == 0) out[b * On + o] = acc + __ldg(bout + o);
        }
    } else if (blockIdx.x < 64) {
        const int b = blockIdx.x - 32;
        for (int i = tid; i < Hn; i += NTHR)
            out[Bn * On + b * Hn + i] = __ldcg(&g_h[0][b * Hn + i]);
    }
}

// ---------------------------------------------------------------------------
extern "C" void kernel_launch(void* const* d_in, const int* in_sizes, int n_in,
                              void* d_out, int out_size)
{
    const float* sentence = (const float*)d_in[0];
    const float* Wl   = (const float*)d_in[1];
    const float* Wg   = (const float*)d_in[2];
    const float* W    = (const float*)d_in[3];
    const float* bias = (const float*)d_in[4];
    const float* Wout = (const float*)d_in[5];
    const float* bout = (const float*)d_in[6];
    float* out = (float*)d_out;

    const int smem = 32 * IH * sizeof(float);  // 65536
    cudaFuncSetAttribute(persist_kernel, cudaFuncAttributeMaxDynamicSharedMemorySize, smem);

    init_kernel<<<32, 256>>>();
    persist_kernel<<<NBLK, NTHR, smem>>>(sentence, Wl, Wg, W, bias, Wout, bout, out);
}